// round 6
// baseline (speedup 1.0000x reference)
#include <cuda_runtime.h>

typedef unsigned long long u64;
typedef unsigned int u32;

#define HW (512*512)

// ---------------- device scratch ----------------
// Max table: 256 pairs over all 512 lights (h only):
//   g_mtab_a[mp*4] = {hx0,hx1,hy0,hy1},  g_mtab_z[mp*2] = {hz0,hz1}
__device__ __align__(16) float g_mtab_a[256 * 4];
__device__ __align__(16) float g_mtab_z[256 * 2];
// Shade table: per batch, 240 pairs (eh>=1 only, 480 lights) * 12 floats (3 float4):
//   [hx0,hx1,hy0,hy1][hz0,hz1,wr0,wr1][wg0,wg1,wb0,wb1],  w = env*sin(phi)/60
__device__ __align__(16) float g_stab[2 * 240 * 12];
__device__ u32 g_maxbits;

// ---------------- packed f32x2 helpers ----------------
__device__ __forceinline__ u64 pk2(float lo, float hi) {
    u64 r;
    asm("mov.b64 %0, {%1, %2};" : "=l"(r) : "r"(__float_as_uint(lo)), "r"(__float_as_uint(hi)));
    return r;
}
__device__ __forceinline__ void unpk2(u64 v, float& lo, float& hi) {
    u32 a, b;
    asm("mov.b64 {%0, %1}, %2;" : "=r"(a), "=r"(b) : "l"(v));
    lo = __uint_as_float(a); hi = __uint_as_float(b);
}
__device__ __forceinline__ u64 dup2(float x) { return pk2(x, x); }
__device__ __forceinline__ u64 fma2_(u64 a, u64 b, u64 c) {
    u64 d; asm("fma.rn.f32x2 %0, %1, %2, %3;" : "=l"(d) : "l"(a), "l"(b), "l"(c)); return d;
}
__device__ __forceinline__ u64 mul2_(u64 a, u64 b) {
    u64 d; asm("mul.rn.f32x2 %0, %1, %2;" : "=l"(d) : "l"(a), "l"(b)); return d;
}
// packed relu: bits(relu(x)) == max_s32(bits(x), 0)
__device__ __forceinline__ u64 relu2(u64 s) {
    u32 lo, hi;
    asm("mov.b64 {%0,%1}, %2;" : "=r"(lo), "=r"(hi) : "l"(s));
    asm("max.s32 %0, %0, 0;" : "+r"(lo));
    asm("max.s32 %0, %0, 0;" : "+r"(hi));
    u64 r;
    asm("mov.b64 %0, {%1,%2};" : "=l"(r) : "r"(lo), "r"(hi));
    return r;
}
// packed running-max (halves of m >= 0, so s32 max == float max)
__device__ __forceinline__ u64 max2_s32(u64 m, u64 s) {
    u32 ml, mh, sl, sh;
    asm("mov.b64 {%0,%1}, %2;" : "=r"(ml), "=r"(mh) : "l"(m));
    asm("mov.b64 {%0,%1}, %2;" : "=r"(sl), "=r"(sh) : "l"(s));
    asm("max.s32 %0, %0, %1;" : "+r"(ml) : "r"(sl));
    asm("max.s32 %0, %0, %1;" : "+r"(mh) : "r"(sh));
    u64 r;
    asm("mov.b64 %0, {%1,%2};" : "=l"(r) : "r"(ml), "r"(mh));
    return r;
}
// MUFU approx funcs
__device__ __forceinline__ float lg2a(float x) {
    float y; asm("lg2.approx.f32 %0, %1;" : "=f"(y) : "f"(x)); return y;
}
__device__ __forceinline__ float ex2a(float x) {
    float y; asm("ex2.approx.f32 %0, %1;" : "=f"(y) : "f"(x)); return y;
}
// relu(x)^64 via MUFU pipe: lg2(0) = -inf -> ex2(-inf) = 0, so x<=0 gives exactly 0
__device__ __forceinline__ float pow64_mufu(float x) {
    return ex2a(64.0f * lg2a(fmaxf(x, 0.0f)));
}

// ---------------- kernel 0: constants + tables + scratch reset ----------------
__global__ void k_setup(const float* __restrict__ env) {
    int m = threadIdx.x;              // 0..511
    if (m == 0) g_maxbits = 0u;

    int eh = m >> 5, ew = m & 31;
    const float PI_F = 3.14159274101257324e+00f;
    float phi = ((float)eh * (1.0f / 16.0f)) * PI_F;
    float th  = (((float)ew * (1.0f / 32.0f)) * 2.0f) * PI_F;

    float sp = sinf(phi), cp = cosf(phi);
    float st = sinf(th),  ct = cosf(th);

    // l = (st*sp, cp, -ct*sp); v = (0,0,1); h = normalize(v + l)
    float hx = st * sp;
    float hy = cp;
    float hz = 1.0f - ct * sp;
    float nrm = sqrtf(hx * hx + hy * hy + hz * hz);
    float rin = 1.0f / nrm;
    hx *= rin; hy *= rin; hz *= rin;

    // max table (all 512 lights)
    {
        int mp = m >> 1, half = m & 1;
        g_mtab_a[mp * 4 + 0 + half] = hx;
        g_mtab_a[mp * 4 + 2 + half] = hy;
        g_mtab_z[mp * 2 + half]     = hz;
    }

    // shade table (eh >= 1 only: 480 lights -> 240 pairs)
    if (m >= 32) {
        int i = m - 32, j = i >> 1, half = i & 1;
        const float SC = (float)(1.0 / 60.0);
        float sw = sp * SC;
        #pragma unroll
        for (int b = 0; b < 2; ++b) {
            float* row = g_stab + (b * 240 + j) * 12;
            row[0 + half]  = hx;
            row[2 + half]  = hy;
            row[4 + half]  = hz;
            const float* e = env + (b * 512 + m) * 3;
            row[6 + half]  = e[0] * sw;
            row[8 + half]  = e[1] * sw;
            row[10 + half] = e[2] * sw;
        }
    }
}

// ---------------- per-pixel normal prep ----------------
__device__ __forceinline__ void load_normal(const float* __restrict__ nptr,
                                            float& nx, float& ny, float& nz) {
    float c0 = nptr[0], c1 = nptr[1], c2 = nptr[2];
    nx = (c2 - 0.5f) * 2.0f;
    ny = (c1 - 0.5f) * 2.0f;
    nz = (c0 - 0.5f) * 2.0f;
    float nn = sqrtf(nx * nx + ny * ny + nz * nz);
    float iv = 1.0f / fmaxf(nn, 1e-12f);
    nx *= iv; ny *= iv; nz *= iv;
}

// ---------------- kernel 1: global max of relu(dot), 2 pixels/thread ----------------
__global__ void __launch_bounds__(256, 2) k_max(const float* __restrict__ normal) {
    __shared__ __align__(16) float4 ta[256];  // hx pair, hy pair
    __shared__ __align__(16) u64   tz[256];   // hz pair
    __shared__ float wm[8];
    for (int i = threadIdx.x; i < 256; i += 256) {
        ta[i] = ((const float4*)g_mtab_a)[i];
        tz[i] = ((const u64*)g_mtab_z)[i];
    }
    __syncthreads();

    int p0 = blockIdx.x * 256 + threadIdx.x;     // grid 1024 -> 0..262143
    int p1 = p0 + 262144;
    float ax, ay, az, bx, by, bz;
    load_normal(normal + p0 * 3, ax, ay, az);
    load_normal(normal + p1 * 3, bx, by, bz);
    u64 ax2 = dup2(ax), ay2 = dup2(ay), az2 = dup2(az);
    u64 bx2 = dup2(bx), by2 = dup2(by), bz2 = dup2(bz);

    u64 ma = 0ull, mb = 0ull;
    #pragma unroll 8
    for (int mp = 0; mp < 256; ++mp) {
        float4 q = ta[mp];
        u64 hx01 = pk2(q.x, q.y), hy01 = pk2(q.z, q.w), hz01 = tz[mp];
        u64 sa = fma2_(ax2, hx01, fma2_(ay2, hy01, mul2_(az2, hz01)));
        u64 sb = fma2_(bx2, hx01, fma2_(by2, hy01, mul2_(bz2, hz01)));
        ma = max2_s32(ma, sa);
        mb = max2_s32(mb, sb);
    }

    u64 mm = max2_s32(ma, mb);
    float l0, h0;
    unpk2(mm, l0, h0);
    float mx = fmaxf(l0, h0);

    #pragma unroll
    for (int o = 16; o; o >>= 1) mx = fmaxf(mx, __shfl_xor_sync(0xffffffffu, mx, o));
    if ((threadIdx.x & 31) == 0) wm[threadIdx.x >> 5] = mx;
    __syncthreads();
    if (threadIdx.x == 0) {
        float m2 = wm[0];
        #pragma unroll
        for (int i = 1; i < 8; ++i) m2 = fmaxf(m2, wm[i]);
        atomicMax(&g_maxbits, __float_as_uint(m2));  // nonneg float bits monotone as uint
    }
}

// ---------------- shade inner-path helpers ----------------
struct Acc { u64 r, g, b; };

__device__ __forceinline__ void chain_pair(const float4* __restrict__ row,
                                           u64 ax2, u64 ay2, u64 az2,
                                           u64 bx2, u64 by2, u64 bz2,
                                           Acc& A0, Acc& A1) {
    float4 q0 = row[0], q1 = row[1], q2 = row[2];
    u64 hx = pk2(q0.x, q0.y), hy = pk2(q0.z, q0.w), hz = pk2(q1.x, q1.y);
    u64 wr = pk2(q1.z, q1.w), wg = pk2(q2.x, q2.y), wb = pk2(q2.z, q2.w);

    u64 sa = fma2_(ax2, hx, fma2_(ay2, hy, mul2_(az2, hz)));
    u64 ua = relu2(sa);
    u64 ca = mul2_(ua, ua);
    ca = mul2_(ca, ca); ca = mul2_(ca, ca); ca = mul2_(ca, ca);
    ca = mul2_(ca, ca); ca = mul2_(ca, ca);
    A0.r = fma2_(ca, wr, A0.r); A0.g = fma2_(ca, wg, A0.g); A0.b = fma2_(ca, wb, A0.b);

    u64 sb = fma2_(bx2, hx, fma2_(by2, hy, mul2_(bz2, hz)));
    u64 ub = relu2(sb);
    u64 cb = mul2_(ub, ub);
    cb = mul2_(cb, cb); cb = mul2_(cb, cb); cb = mul2_(cb, cb);
    cb = mul2_(cb, cb); cb = mul2_(cb, cb);
    A1.r = fma2_(cb, wr, A1.r); A1.g = fma2_(cb, wg, A1.g); A1.b = fma2_(cb, wb, A1.b);
}

__device__ __forceinline__ void mufu_pair(const float4* __restrict__ row,
                                          u64 ax2, u64 ay2, u64 az2,
                                          u64 bx2, u64 by2, u64 bz2,
                                          Acc& A0, Acc& A1) {
    float4 q0 = row[0], q1 = row[1], q2 = row[2];
    u64 hx = pk2(q0.x, q0.y), hy = pk2(q0.z, q0.w), hz = pk2(q1.x, q1.y);
    u64 wr = pk2(q1.z, q1.w), wg = pk2(q2.x, q2.y), wb = pk2(q2.z, q2.w);

    u64 sa = fma2_(ax2, hx, fma2_(ay2, hy, mul2_(az2, hz)));
    float s0, s1; unpk2(sa, s0, s1);
    u64 ca = pk2(pow64_mufu(s0), pow64_mufu(s1));
    A0.r = fma2_(ca, wr, A0.r); A0.g = fma2_(ca, wg, A0.g); A0.b = fma2_(ca, wb, A0.b);

    u64 sb = fma2_(bx2, hx, fma2_(by2, hy, mul2_(bz2, hz)));
    float t0, t1; unpk2(sb, t0, t1);
    u64 cb = pk2(pow64_mufu(t0), pow64_mufu(t1));
    A1.r = fma2_(cb, wr, A1.r); A1.g = fma2_(cb, wg, A1.g); A1.b = fma2_(cb, wb, A1.b);
}

// ---------------- kernel 2: fused shade, 2 pixels/thread, 240 pairs ----------------
// 48 outer iters x 5 pairs: 2 chain-path (fma pipe) + 3 MUFU-path -> both pipes ~balanced
__global__ void __launch_bounds__(256, 2) k_shade(const float* __restrict__ normal,
                                                  float* __restrict__ out) {
    __shared__ __align__(16) float4 tab[720];   // 240 pairs * 3 float4 = 11.25KB
    int b = blockIdx.y;
    const float4* gt = (const float4*)g_stab + b * 720;
    for (int i = threadIdx.x; i < 720; i += 256) tab[i] = gt[i];
    __syncthreads();

    int i0 = blockIdx.x * 256 + threadIdx.x;     // 0..131071 within batch
    int i1 = i0 + 131072;

    float gm = __uint_as_float(g_maxbits);
    float sc = 1.0f / gm;                        // fold 1/max into the normal

    float ax, ay, az, bx, by, bz;
    load_normal(normal + (b * HW + i0) * 3, ax, ay, az);
    load_normal(normal + (b * HW + i1) * 3, bx, by, bz);
    u64 ax2 = dup2(ax * sc), ay2 = dup2(ay * sc), az2 = dup2(az * sc);
    u64 bx2 = dup2(bx * sc), by2 = dup2(by * sc), bz2 = dup2(bz * sc);

    Acc A0 = {0ull, 0ull, 0ull}, A1 = {0ull, 0ull, 0ull};

    #pragma unroll 1
    for (int t = 0; t < 48; ++t) {
        const float4* base = &tab[t * 15];
        chain_pair(base + 0,  ax2, ay2, az2, bx2, by2, bz2, A0, A1);
        chain_pair(base + 3,  ax2, ay2, az2, bx2, by2, bz2, A0, A1);
        mufu_pair (base + 6,  ax2, ay2, az2, bx2, by2, bz2, A0, A1);
        mufu_pair (base + 9,  ax2, ay2, az2, bx2, by2, bz2, A0, A1);
        mufu_pair (base + 12, ax2, ay2, az2, bx2, by2, bz2, A0, A1);
    }

    float r0, r1, g0, g1, bb0, bb1;
    int ob = b * 3 * HW;
    unpk2(A0.r, r0, r1); unpk2(A0.g, g0, g1); unpk2(A0.b, bb0, bb1);
    out[ob + i0]          = r0 + r1;
    out[ob + HW + i0]     = g0 + g1;
    out[ob + 2 * HW + i0] = bb0 + bb1;
    unpk2(A1.r, r0, r1); unpk2(A1.g, g0, g1); unpk2(A1.b, bb0, bb1);
    out[ob + i1]          = r0 + r1;
    out[ob + HW + i1]     = g0 + g1;
    out[ob + 2 * HW + i1] = bb0 + bb1;
}

// ---------------- launch ----------------
extern "C" void kernel_launch(void* const* d_in, const int* in_sizes, int n_in,
                              void* d_out, int out_size) {
    const float* env    = (const float*)d_in[0];
    const float* normal = (const float*)d_in[1];
    if (n_in >= 2 && in_sizes[0] > in_sizes[1]) {
        env    = (const float*)d_in[1];
        normal = (const float*)d_in[0];
    }
    k_setup<<<1, 512>>>(env);
    k_max<<<1024, 256>>>(normal);
    k_shade<<<dim3(512, 2), 256>>>(normal, (float*)d_out);
}